// round 16
// baseline (speedup 1.0000x reference)
#include <cuda_runtime.h>
#include <cuda_bf16.h>
#include <cstdint>

// ----------------------------------------------------------------------------
// Problem constants
// ----------------------------------------------------------------------------
#define NROWS   12544          // 16*28*28 feature rows
#define MROWS   16384          // memory bank rows
#define KDIM    1536           // feature dim (512 + 1024)
#define BATCH   16
#define HW28    784            // 28*28
#define OUTHW   50176          // 224*224

// GEMM tiling: CTA 128x128x64, 8 warps (2x4), warp tile 64x32  (champion)
#define BM      128
#define BN      128
#define BK      64
#define NKT     (KDIM / BK)    // 24 k-iterations (divisible by 3)
#define STAGES  3
#define STAGE_A_BYTES  16384           // 128 x 64 bf16 (128B rows)
#define STAGE_B_BYTES  16384           // 128 x 64 bf16
#define STAGE_BYTES    (STAGE_A_BYTES + STAGE_B_BYTES)   // 32768
#define SMEM_MSQ_OFF   (STAGES * STAGE_BYTES)            // 98304
#define SMEM_XSQ_OFF   (SMEM_MSQ_OFF + BN * 4)           // 98816
#define SMEM_TOTAL     (SMEM_XSQ_OFF + BM * 4)           // 99328

// fused prep kernel block partition
#define T2_BLOCKS  3200        // 25 hw-tiles x 8 c-tiles x 16 b
#define T3_BLOCKS  512         // 32 c-chunks x 16 b
#define MB_BLOCKS  (MROWS / 8) // warp-per-row, 8 rows per block
#define PREP_BLOCKS (T2_BLOCKS + T3_BLOCKS + MB_BLOCKS)  // 5760

// ----------------------------------------------------------------------------
// Device scratch (static globals: no allocation anywhere)
// ----------------------------------------------------------------------------
__device__ __nv_bfloat16 g_feats[(size_t)NROWS * KDIM];   // 38.5 MB
__device__ float         g_xsq[NROWS];
__device__ __nv_bfloat16 g_mb[(size_t)MROWS * KDIM];      // 50.3 MB
__device__ float         g_msq[MROWS];
__device__ unsigned      g_minbits[NROWS];                // min d2 as uint bits

// ----------------------------------------------------------------------------
// Helpers
// ----------------------------------------------------------------------------
__device__ __forceinline__ uint32_t smem_u32(const void* p) {
    uint32_t a;
    asm("{ .reg .u64 t; cvta.to.shared.u64 t, %1; cvt.u32.u64 %0, t; }"
        : "=r"(a) : "l"(p));
    return a;
}
// SW128 swizzle for 128-byte rows: bits[6:4] ^= bits[9:7]
__device__ __forceinline__ uint32_t swz128(uint32_t off) {
    return off ^ ((off >> 3) & 0x70);
}
__device__ __forceinline__ void cp_async16(uint32_t dst, const void* src) {
    asm volatile("cp.async.cg.shared.global [%0], [%1], 16;\n"
                 :: "r"(dst), "l"(src) : "memory");
}
__device__ __forceinline__ void ldmx4(uint32_t* r, uint32_t addr) {
    asm volatile("ldmatrix.sync.aligned.m8n8.x4.shared.b16 {%0,%1,%2,%3}, [%4];"
                 : "=r"(r[0]), "=r"(r[1]), "=r"(r[2]), "=r"(r[3]) : "r"(addr));
}
__device__ __forceinline__ void mma16816(float* d, const uint32_t* a,
                                         uint32_t b0, uint32_t b1) {
    asm volatile(
        "mma.sync.aligned.m16n8k16.row.col.f32.bf16.bf16.f32 "
        "{%0,%1,%2,%3}, {%4,%5,%6,%7}, {%8,%9}, {%0,%1,%2,%3};"
        : "+f"(d[0]), "+f"(d[1]), "+f"(d[2]), "+f"(d[3])
        : "r"(a[0]), "r"(a[1]), "r"(a[2]), "r"(a[3]), "r"(b0), "r"(b1));
}

// ----------------------------------------------------------------------------
// Fused prep kernel: t2-transpose | t3-upsample | bank-convert, dispatched on
// blockIdx.x so the three independent streams overlap in one launch.
// Block 0 additionally zero-inits the pred-score slots of the output.
// ----------------------------------------------------------------------------
__global__ void __launch_bounds__(256) prep_fused(const float* __restrict__ f2,
                                                  const float* __restrict__ f3,
                                                  const float* __restrict__ mb,
                                                  float* __restrict__ out) {
    __shared__ float sh[32 * 197];         // 25.2 KB, used per-role
    const int bid = blockIdx.x;
    const int tid = threadIdx.x;

    if (bid == 0 && tid < BATCH)
        out[(size_t)BATCH * OUTHW + tid] = 0.f;   // pred init for atomicMax

    if (bid < T2_BLOCKS) {
        // ---- feat2 transpose: [b,512,784] -> g_feats[.][0..512) ----
        float (*t)[33] = (float(*)[33])sh;     // 64 x 33
        const int hw0 = (bid % 25) * 32;
        const int c0  = ((bid / 25) & 7) * 64;
        const int b   = bid / 200;

        #pragma unroll
        for (int it = 0; it < 8; it++) {
            int idx = it * 256 + tid;          // 2048 = 64c x 32hw
            int cl = idx >> 5, hl = idx & 31;
            int hw = hw0 + hl;
            if (hw < HW28)
                t[cl][hl] = f2[((size_t)b * 512 + c0 + cl) * HW28 + hw];
        }
        __syncthreads();
        // write phase: channel PAIRS as uint32 (coalesced 128B per warp)
        #pragma unroll
        for (int it = 0; it < 4; it++) {
            int idx = it * 256 + tid;          // 1024 = 32 cpair x 32 hw
            int cp = idx & 31, hl = idx >> 5;  // c = 2*cp fast -> coalesced
            int hw = hw0 + hl;
            if (hw < HW28) {
                __nv_bfloat162 h2 = __floats2bfloat162_rn(t[2 * cp][hl],
                                                          t[2 * cp + 1][hl]);
                *(uint32_t*)&g_feats[(size_t)(b * HW28 + hw) * KDIM + c0 + 2 * cp]
                    = *(uint32_t*)&h2;
            }
        }
    } else if (bid < T2_BLOCKS + T3_BLOCKS) {
        // ---- feat3 bilinear 14->28 + transpose -> g_feats[.][512+) ----
        float (*plane)[197] = (float(*)[197])sh;   // 32 x 197
        const int t3i = bid - T2_BLOCKS;
        const int cb = (t3i & 31) * 32;
        const int b  = t3i >> 5;

        #pragma unroll
        for (int it = 0; it < 25; it++) {      // 32*196 = 6272
            int idx = it * 256 + tid;
            if (idx < 32 * 196) {
                int cl = idx / 196, p = idx - cl * 196;
                plane[cl][p] = f3[((size_t)b * 1024 + cb + cl) * 196 + p];
            }
        }
        __syncthreads();

        // each thread: one hw position x one channel PAIR (shared weights)
        for (int it = 0; it < 49; it++) {      // 784 hw * 16 cpair = 12544
            int idx = it * 256 + tid;
            int hw = idx >> 4, cp = idx & 15;
            int h = hw / 28, w = hw - (hw / 28) * 28;
            float sy = h * 0.5f - 0.25f;
            float sx = w * 0.5f - 0.25f;
            float fy0 = floorf(sy), fx0 = floorf(sx);
            float wy = sy - fy0, wx = sx - fx0;
            int y0 = (int)fy0, x0 = (int)fx0;
            int y0c = max(0, min(13, y0)),   y1c = max(0, min(13, y0 + 1));
            int x0c = max(0, min(13, x0)),   x1c = max(0, min(13, x0 + 1));
            int p00 = y0c * 14 + x0c, p01 = y0c * 14 + x1c;
            int p10 = y1c * 14 + x0c, p11 = y1c * 14 + x1c;
            float w00 = (1.f - wy) * (1.f - wx), w01 = (1.f - wy) * wx;
            float w10 = wy * (1.f - wx),         w11 = wy * wx;
            int cl = 2 * cp;
            float va = w00 * plane[cl][p00] + w01 * plane[cl][p01]
                     + w10 * plane[cl][p10] + w11 * plane[cl][p11];
            float vb = w00 * plane[cl + 1][p00] + w01 * plane[cl + 1][p01]
                     + w10 * plane[cl + 1][p10] + w11 * plane[cl + 1][p11];
            __nv_bfloat162 h2 = __floats2bfloat162_rn(va, vb);
            *(uint32_t*)&g_feats[(size_t)(b * HW28 + hw) * KDIM + 512 + cb + cl]
                = *(uint32_t*)&h2;
        }
    } else {
        // ---- memory_bank: warp-per-row -> bf16 + m_sq (12 float4 per lane) --
        const int lane = tid & 31;
        const int j = (bid - (T2_BLOCKS + T3_BLOCKS)) * 8 + (tid >> 5);
        const float4* src = (const float4*)(mb + (size_t)j * KDIM);
        uint2* dst = (uint2*)(g_mb + (size_t)j * KDIM);
        float s = 0.f;
        #pragma unroll
        for (int it = 0; it < 12; it++) {      // 384 float4 per row / 32 lanes
            int i = lane + it * 32;
            float4 v = src[i];
            s = fmaf(v.x, v.x, fmaf(v.y, v.y, fmaf(v.z, v.z, fmaf(v.w, v.w, s))));
            __nv_bfloat162 lo = __floats2bfloat162_rn(v.x, v.y);
            __nv_bfloat162 hi = __floats2bfloat162_rn(v.z, v.w);
            uint2 o;
            o.x = *(uint32_t*)&lo;
            o.y = *(uint32_t*)&hi;
            dst[i] = o;
        }
        #pragma unroll
        for (int o = 16; o > 0; o >>= 1) s += __shfl_xor_sync(0xffffffffu, s, o);
        if (lane == 0) g_msq[j] = s;
    }
}

// ----------------------------------------------------------------------------
// Kernel XQ: x_sq from bf16 feats + min-buffer init. Warp per row.
// grid 12544/8, 256 thr.
// ----------------------------------------------------------------------------
__global__ void __launch_bounds__(256) xsq_kernel() {
    const int wid = threadIdx.x >> 5, lane = threadIdx.x & 31;
    const int n = blockIdx.x * 8 + wid;
    const uint4* row = (const uint4*)(g_feats + (size_t)n * KDIM);
    float s = 0.f;
    #pragma unroll
    for (int it = 0; it < 6; it++) {       // 192 uint4 per row / 32 lanes
        uint4 u = row[lane + it * 32];
        const __nv_bfloat162* h = (const __nv_bfloat162*)&u;
        #pragma unroll
        for (int j = 0; j < 4; j++) {      // uint4 = 4 x bf16x2
            float2 f = __bfloat1622float2(h[j]);
            s = fmaf(f.x, f.x, s);
            s = fmaf(f.y, f.y, s);
        }
    }
    #pragma unroll
    for (int o = 16; o > 0; o >>= 1) s += __shfl_xor_sync(0xffffffffu, s, o);
    if (lane == 0) {
        g_xsq[n] = s;
        g_minbits[n] = 0x7F7FFFFFu;        // FLT_MAX bits
    }
}

// ----------------------------------------------------------------------------
// Kernel GEMM: pipelined bf16 mma.sync with fused row-min epilogue.
// Champion config (2 CTAs/SM x 8 warps): per kt: wait+sync, preload ks0
// frags, issue stage kt+2 into the ldmatrix latency window, 4 k16 groups with
// fragment double-buffering. kt loop unrolled x3 for compile-time selectors.
// msq AND xsq staged into smem after the cp.async prologue, so the epilogue
// has no global loads on the CTA-retire critical path.
// grid (98, 128), 256 threads.
// ----------------------------------------------------------------------------
__global__ void __launch_bounds__(256, 2) gemm_min_fb() {
    extern __shared__ char smem[];
    const int tid = threadIdx.x;
    const int wid = tid >> 5, lane = tid & 31;
    const int row_base = blockIdx.x * BM;
    const int n_base = blockIdx.y * BN;
    float* msq_s = (float*)(smem + SMEM_MSQ_OFF);
    float* xsq_s = (float*)(smem + SMEM_XSQ_OFF);
    const uint32_t sb = smem_u32(smem);

    // per-lane ldmatrix byte offsets within a tile, per k16 step ks=0..3
    uint32_t a_off[4], b_off[4];
    {
        uint32_t arow = (uint32_t)((lane & 15) * 128 + (lane >> 4) * 16);
        uint32_t brow = (uint32_t)((((lane >> 4) << 3) + (lane & 7)) * 128
                                   + ((lane >> 3) & 1) * 16);
        #pragma unroll
        for (int ks = 0; ks < 4; ks++) {
            a_off[ks] = swz128(arow + ks * 32);
            b_off[ks] = swz128(brow + ks * 32);
        }
    }
    const int mbw = (wid >> 2) * 64;   // warp m base
    const int nbw = (wid & 3) * 32;    // warp n base

    float acc[4][4][4];
    #pragma unroll
    for (int mi = 0; mi < 4; mi++)
        #pragma unroll
        for (int ni = 0; ni < 4; ni++)
            #pragma unroll
            for (int j = 0; j < 4; j++) acc[mi][ni][j] = 0.f;

    // one pipeline stage: A 128x64 + B 128x64 bf16 = 2048 x 16B transfers
    auto issue_stage = [&](int kt, int bsel) {
        uint32_t abase = sb + (uint32_t)(bsel * STAGE_BYTES);
        uint32_t bbase = abase + STAGE_A_BYTES;
        int kb = kt * BK;
        #pragma unroll
        for (int h = 0; h < 8; h++) {
            int i = tid + h * 256;
            int r = (i >> 3) & 127, s = i & 7;
            uint32_t doff = swz128((uint32_t)(r * 128 + s * 16));
            if (i < 1024) {
                cp_async16(abase + doff,
                           g_feats + (size_t)(row_base + r) * KDIM + kb + s * 8);
            } else {
                cp_async16(bbase + doff,
                           g_mb + (size_t)(n_base + r) * KDIM + kb + s * 8);
            }
        }
    };

    uint32_t ar[2][4][4], br[2][2][4];
    auto load_frags = [&](int buf, uint32_t awarp, uint32_t bwarp, int ks) {
        #pragma unroll
        for (int mi = 0; mi < 4; mi++)
            ldmx4(ar[buf][mi], awarp + (uint32_t)(mi * 16 * 128) + a_off[ks]);
        #pragma unroll
        for (int nb = 0; nb < 2; nb++)
            ldmx4(br[buf][nb], bwarp + (uint32_t)(nb * 16 * 128) + b_off[ks]);
    };
    auto do_mma = [&](int buf) {
        #pragma unroll
        for (int mi = 0; mi < 4; mi++)
            #pragma unroll
            for (int ni = 0; ni < 4; ni++)
                mma16816(acc[mi][ni], ar[buf][mi],
                         br[buf][ni >> 1][(ni & 1) * 2],
                         br[buf][ni >> 1][(ni & 1) * 2 + 1]);
    };

    // per-kt body, bsel = kt % STAGES as a compile-time constant at call site
    auto body = [&](int kt, int bsel) {
        asm volatile("cp.async.wait_group 1;" ::: "memory");
        __syncthreads();

        uint32_t abase = sb + (uint32_t)(bsel * STAGE_BYTES);
        uint32_t awarp = abase + (uint32_t)(mbw * 128);
        uint32_t bwarp = abase + STAGE_A_BYTES + (uint32_t)(nbw * 128);

        // preload ks0 fragments first...
        load_frags(0, awarp, bwarp, 0);

        // ...then fill the ldmatrix latency window with cp.async issue
        if (kt + 2 < NKT) issue_stage(kt + 2, (bsel + 2) % STAGES);
        asm volatile("cp.async.commit_group;" ::: "memory");

        #pragma unroll
        for (int ks = 0; ks < 4; ks++) {
            int cur = ks & 1, nxt = cur ^ 1;
            if (ks < 3) load_frags(nxt, awarp, bwarp, ks + 1);
            do_mma(cur);
        }
    };

    // prologue: 2 stages in flight, then stage msq + xsq (epilogue-only data)
    issue_stage(0, 0); asm volatile("cp.async.commit_group;" ::: "memory");
    issue_stage(1, 1); asm volatile("cp.async.commit_group;" ::: "memory");
    for (int i = tid; i < BN; i += 256) msq_s[i] = g_msq[n_base + i];
    if (tid < BM) xsq_s[tid] = g_xsq[row_base + tid];

    #pragma unroll 1
    for (int kt0 = 0; kt0 < NKT; kt0 += 3) {   // NKT = 24, divisible by 3
        body(kt0 + 0, 0);
        body(kt0 + 1, 1);
        body(kt0 + 2, 2);
    }

    // epilogue: q = min_n (m_sq[n] - 2*dot); d2 = max(xsq + q, 0); atomicMin
    // (msq_s/xsq_s writes were ordered by the mainloop's __syncthreads)
    #pragma unroll
    for (int mi = 0; mi < 4; mi++) {
        float q0 = 3.4e38f, q1 = 3.4e38f;
        #pragma unroll
        for (int ni = 0; ni < 4; ni++) {
            int n = nbw + ni * 8 + (lane & 3) * 2;
            float ms0 = msq_s[n], ms1 = msq_s[n + 1];
            q0 = fminf(q0, fminf(fmaf(-2.f, acc[mi][ni][0], ms0),
                                 fmaf(-2.f, acc[mi][ni][1], ms1)));
            q1 = fminf(q1, fminf(fmaf(-2.f, acc[mi][ni][2], ms0),
                                 fmaf(-2.f, acc[mi][ni][3], ms1)));
        }
        q0 = fminf(q0, __shfl_xor_sync(0xffffffffu, q0, 1));
        q0 = fminf(q0, __shfl_xor_sync(0xffffffffu, q0, 2));
        q1 = fminf(q1, __shfl_xor_sync(0xffffffffu, q1, 1));
        q1 = fminf(q1, __shfl_xor_sync(0xffffffffu, q1, 2));
        if ((lane & 3) == 0) {
            int l0 = mbw + mi * 16 + (lane >> 2);
            int l1 = l0 + 8;
            float d0 = fmaxf(xsq_s[l0] + q0, 0.f);
            float d1 = fmaxf(xsq_s[l1] + q1, 0.f);
            atomicMin(&g_minbits[row_base + l0], __float_as_uint(d0));
            atomicMin(&g_minbits[row_base + l1], __float_as_uint(d1));
        }
    }
}

// ----------------------------------------------------------------------------
// Kernel 4: sqrt + bilinear 28->224 + per-batch max (atomicMax on f32 bits).
// grid (16 slices, 16 batches), 256 thr. Each block stages ONLY the <=5-row
// s28 window its 14 output rows touch.
// Output: [0, 16*50176) anomaly map, [16*50176, +16) pred scores.
// ----------------------------------------------------------------------------
__global__ void __launch_bounds__(256) finalize_kernel(float* __restrict__ out) {
    const int slice = blockIdx.x;          // 0..15 -> rows [slice*14, +14)
    const int b = blockIdx.y;
    const int tid = threadIdx.x;
    __shared__ float sw[6 * 28];           // staged source window
    __shared__ float sred[256];

    // source-row window for output rows [slice*14, slice*14+14):
    // sy in [1.75*slice - 0.4375, 1.75*slice + 1.1875]
    const int y_lo = max(0, (int)floorf(slice * 1.75f - 0.4375f));
    const int y_hi = min(27, (int)floorf(slice * 1.75f + 1.1875f) + 1);
    const int wrows = y_hi - y_lo + 1;     // <= 4

    if (tid < wrows * 28)
        sw[tid] = sqrtf(__uint_as_float(
            g_minbits[b * HW28 + (y_lo + tid / 28) * 28 + (tid % 28)]));
    __syncthreads();

    float mx = 0.f;
    float* omap = out + (size_t)b * OUTHW;
    const int p0 = slice * 3136, p1 = p0 + 3136;   // 14 rows x 224
    for (int p = p0 + tid; p < p1; p += 256) {
        int i = p / 224, j = p - (p / 224) * 224;
        float sy = i * 0.125f - 0.4375f;
        float sx = j * 0.125f - 0.4375f;
        float fy0 = floorf(sy), fx0 = floorf(sx);
        float wy = sy - fy0, wx = sx - fx0;
        int y0 = (int)fy0, x0 = (int)fx0;
        int y0c = max(0, min(27, y0)) - y_lo,  y1c = max(0, min(27, y0 + 1)) - y_lo;
        int x0c = max(0, min(27, x0)),         x1c = max(0, min(27, x0 + 1));
        float v00 = sw[y0c * 28 + x0c], v01 = sw[y0c * 28 + x1c];
        float v10 = sw[y1c * 28 + x0c], v11 = sw[y1c * 28 + x1c];
        float v = (1.f - wy) * ((1.f - wx) * v00 + wx * v01)
                +        wy  * ((1.f - wx) * v10 + wx * v11);
        omap[p] = v;
        mx = fmaxf(mx, v);
    }
    sred[tid] = mx;
    __syncthreads();
    for (int s = 128; s > 0; s >>= 1) {
        if (tid < s) sred[tid] = fmaxf(sred[tid], sred[tid + s]);
        __syncthreads();
    }
    if (tid == 0)  // values >= 0, so uint-bit compare == float compare
        atomicMax((unsigned*)&out[(size_t)BATCH * OUTHW + b],
                  __float_as_uint(sred[0]));
}

// ----------------------------------------------------------------------------
// Launch
// ----------------------------------------------------------------------------
extern "C" void kernel_launch(void* const* d_in, const int* in_sizes, int n_in,
                              void* d_out, int out_size) {
    const float* feat2 = (const float*)d_in[0];
    const float* feat3 = (const float*)d_in[1];
    const float* mbank = (const float*)d_in[2];
    float* out = (float*)d_out;

    cudaFuncSetAttribute(gemm_min_fb,
                         cudaFuncAttributeMaxDynamicSharedMemorySize, SMEM_TOTAL);

    prep_fused<<<PREP_BLOCKS, 256>>>(feat2, feat3, mbank, out);
    xsq_kernel<<<NROWS / 8, 256>>>();
    gemm_min_fb<<<dim3(NROWS / BM, MROWS / BN), 256, SMEM_TOTAL>>>();
    finalize_kernel<<<dim3(16, BATCH), 256>>>(out);
}

// round 17
// speedup vs baseline: 1.0318x; 1.0318x over previous
#include <cuda_runtime.h>
#include <cuda_bf16.h>
#include <cstdint>

// ----------------------------------------------------------------------------
// Problem constants
// ----------------------------------------------------------------------------
#define NROWS   12544          // 16*28*28 feature rows
#define MROWS   16384          // memory bank rows
#define KDIM    1536           // feature dim (512 + 1024)
#define BATCH   16
#define HW28    784            // 28*28
#define OUTHW   50176          // 224*224

// GEMM tiling: CTA 128x128x64, 8 warps (2x4), warp tile 64x32  (champion)
#define BM      128
#define BN      128
#define BK      64
#define NKT     (KDIM / BK)    // 24 k-iterations (divisible by 3)
#define STAGES  3
#define STAGE_A_BYTES  16384           // 128 x 64 bf16 (128B rows)
#define STAGE_B_BYTES  16384           // 128 x 64 bf16
#define STAGE_BYTES    (STAGE_A_BYTES + STAGE_B_BYTES)   // 32768
#define SMEM_MSQ_OFF   (STAGES * STAGE_BYTES)            // 98304
#define SMEM_TOTAL     (SMEM_MSQ_OFF + BN * 4)           // 98816

// fused prep kernel block partition
#define T2_BLOCKS  3200        // 25 hw-tiles x 8 c-tiles x 16 b
#define T3_BLOCKS  512         // 32 c-chunks x 16 b
#define MB_BLOCKS  (MROWS / 8) // warp-per-row, 8 rows per block
#define PREP_BLOCKS (T2_BLOCKS + T3_BLOCKS + MB_BLOCKS)  // 5760

// ----------------------------------------------------------------------------
// Device scratch (static globals: no allocation anywhere)
// ----------------------------------------------------------------------------
__device__ __nv_bfloat16 g_feats[(size_t)NROWS * KDIM];   // 38.5 MB
__device__ float         g_xsq[NROWS];
__device__ __nv_bfloat16 g_mb[(size_t)MROWS * KDIM];      // 50.3 MB
__device__ float         g_msq[MROWS];
__device__ unsigned      g_minbits[NROWS];                // min d2 as uint bits

// ----------------------------------------------------------------------------
// Helpers
// ----------------------------------------------------------------------------
__device__ __forceinline__ uint32_t smem_u32(const void* p) {
    uint32_t a;
    asm("{ .reg .u64 t; cvta.to.shared.u64 t, %1; cvt.u32.u64 %0, t; }"
        : "=r"(a) : "l"(p));
    return a;
}
// SW128 swizzle for 128-byte rows: bits[6:4] ^= bits[9:7]
__device__ __forceinline__ uint32_t swz128(uint32_t off) {
    return off ^ ((off >> 3) & 0x70);
}
__device__ __forceinline__ void cp_async16(uint32_t dst, const void* src) {
    asm volatile("cp.async.cg.shared.global [%0], [%1], 16;\n"
                 :: "r"(dst), "l"(src) : "memory");
}
__device__ __forceinline__ void ldmx4(uint32_t* r, uint32_t addr) {
    asm volatile("ldmatrix.sync.aligned.m8n8.x4.shared.b16 {%0,%1,%2,%3}, [%4];"
                 : "=r"(r[0]), "=r"(r[1]), "=r"(r[2]), "=r"(r[3]) : "r"(addr));
}
__device__ __forceinline__ void mma16816(float* d, const uint32_t* a,
                                         uint32_t b0, uint32_t b1) {
    asm volatile(
        "mma.sync.aligned.m16n8k16.row.col.f32.bf16.bf16.f32 "
        "{%0,%1,%2,%3}, {%4,%5,%6,%7}, {%8,%9}, {%0,%1,%2,%3};"
        : "+f"(d[0]), "+f"(d[1]), "+f"(d[2]), "+f"(d[3])
        : "r"(a[0]), "r"(a[1]), "r"(a[2]), "r"(a[3]), "r"(b0), "r"(b1));
}

// ----------------------------------------------------------------------------
// Fused prep kernel: t2-transpose | t3-upsample | bank-convert, dispatched on
// blockIdx.x so the three independent streams overlap in one launch.
// Block 0 additionally zero-inits the pred-score slots of the output.
// ----------------------------------------------------------------------------
__global__ void __launch_bounds__(256) prep_fused(const float* __restrict__ f2,
                                                  const float* __restrict__ f3,
                                                  const float* __restrict__ mb,
                                                  float* __restrict__ out) {
    __shared__ float sh[32 * 197];         // 25.2 KB, used per-role
    const int bid = blockIdx.x;
    const int tid = threadIdx.x;

    if (bid == 0 && tid < BATCH)
        out[(size_t)BATCH * OUTHW + tid] = 0.f;   // pred init for atomicMax

    if (bid < T2_BLOCKS) {
        // ---- feat2 transpose: [b,512,784] -> g_feats[.][0..512) ----
        float (*t)[33] = (float(*)[33])sh;     // 64 x 33
        const int hw0 = (bid % 25) * 32;
        const int c0  = ((bid / 25) & 7) * 64;
        const int b   = bid / 200;

        #pragma unroll
        for (int it = 0; it < 8; it++) {
            int idx = it * 256 + tid;          // 2048 = 64c x 32hw
            int cl = idx >> 5, hl = idx & 31;
            int hw = hw0 + hl;
            if (hw < HW28)
                t[cl][hl] = f2[((size_t)b * 512 + c0 + cl) * HW28 + hw];
        }
        __syncthreads();
        // write phase: channel PAIRS as uint32 (coalesced 128B per warp)
        #pragma unroll
        for (int it = 0; it < 4; it++) {
            int idx = it * 256 + tid;          // 1024 = 32 cpair x 32 hw
            int cp = idx & 31, hl = idx >> 5;  // c = 2*cp fast -> coalesced
            int hw = hw0 + hl;
            if (hw < HW28) {
                __nv_bfloat162 h2 = __floats2bfloat162_rn(t[2 * cp][hl],
                                                          t[2 * cp + 1][hl]);
                *(uint32_t*)&g_feats[(size_t)(b * HW28 + hw) * KDIM + c0 + 2 * cp]
                    = *(uint32_t*)&h2;
            }
        }
    } else if (bid < T2_BLOCKS + T3_BLOCKS) {
        // ---- feat3 bilinear 14->28 + transpose -> g_feats[.][512+) ----
        float (*plane)[197] = (float(*)[197])sh;   // 32 x 197
        const int t3i = bid - T2_BLOCKS;
        const int cb = (t3i & 31) * 32;
        const int b  = t3i >> 5;

        #pragma unroll
        for (int it = 0; it < 25; it++) {      // 32*196 = 6272
            int idx = it * 256 + tid;
            if (idx < 32 * 196) {
                int cl = idx / 196, p = idx - cl * 196;
                plane[cl][p] = f3[((size_t)b * 1024 + cb + cl) * 196 + p];
            }
        }
        __syncthreads();

        // each thread: one hw position x one channel PAIR (shared weights)
        for (int it = 0; it < 49; it++) {      // 784 hw * 16 cpair = 12544
            int idx = it * 256 + tid;
            int hw = idx >> 4, cp = idx & 15;
            int h = hw / 28, w = hw - (hw / 28) * 28;
            float sy = h * 0.5f - 0.25f;
            float sx = w * 0.5f - 0.25f;
            float fy0 = floorf(sy), fx0 = floorf(sx);
            float wy = sy - fy0, wx = sx - fx0;
            int y0 = (int)fy0, x0 = (int)fx0;
            int y0c = max(0, min(13, y0)),   y1c = max(0, min(13, y0 + 1));
            int x0c = max(0, min(13, x0)),   x1c = max(0, min(13, x0 + 1));
            int p00 = y0c * 14 + x0c, p01 = y0c * 14 + x1c;
            int p10 = y1c * 14 + x0c, p11 = y1c * 14 + x1c;
            float w00 = (1.f - wy) * (1.f - wx), w01 = (1.f - wy) * wx;
            float w10 = wy * (1.f - wx),         w11 = wy * wx;
            int cl = 2 * cp;
            float va = w00 * plane[cl][p00] + w01 * plane[cl][p01]
                     + w10 * plane[cl][p10] + w11 * plane[cl][p11];
            float vb = w00 * plane[cl + 1][p00] + w01 * plane[cl + 1][p01]
                     + w10 * plane[cl + 1][p10] + w11 * plane[cl + 1][p11];
            __nv_bfloat162 h2 = __floats2bfloat162_rn(va, vb);
            *(uint32_t*)&g_feats[(size_t)(b * HW28 + hw) * KDIM + 512 + cb + cl]
                = *(uint32_t*)&h2;
        }
    } else {
        // ---- memory_bank: warp-per-row -> bf16 + m_sq (12 float4 per lane) --
        const int lane = tid & 31;
        const int j = (bid - (T2_BLOCKS + T3_BLOCKS)) * 8 + (tid >> 5);
        const float4* src = (const float4*)(mb + (size_t)j * KDIM);
        uint2* dst = (uint2*)(g_mb + (size_t)j * KDIM);
        float s = 0.f;
        #pragma unroll
        for (int it = 0; it < 12; it++) {      // 384 float4 per row / 32 lanes
            int i = lane + it * 32;
            float4 v = src[i];
            s = fmaf(v.x, v.x, fmaf(v.y, v.y, fmaf(v.z, v.z, fmaf(v.w, v.w, s))));
            __nv_bfloat162 lo = __floats2bfloat162_rn(v.x, v.y);
            __nv_bfloat162 hi = __floats2bfloat162_rn(v.z, v.w);
            uint2 o;
            o.x = *(uint32_t*)&lo;
            o.y = *(uint32_t*)&hi;
            dst[i] = o;
        }
        #pragma unroll
        for (int o = 16; o > 0; o >>= 1) s += __shfl_xor_sync(0xffffffffu, s, o);
        if (lane == 0) g_msq[j] = s;
    }
}

// ----------------------------------------------------------------------------
// Kernel XQ: x_sq from bf16 feats + min-buffer init. Warp per row.
// grid 12544/8, 256 thr.
// ----------------------------------------------------------------------------
__global__ void __launch_bounds__(256) xsq_kernel() {
    const int wid = threadIdx.x >> 5, lane = threadIdx.x & 31;
    const int n = blockIdx.x * 8 + wid;
    const uint4* row = (const uint4*)(g_feats + (size_t)n * KDIM);
    float s = 0.f;
    #pragma unroll
    for (int it = 0; it < 6; it++) {       // 192 uint4 per row / 32 lanes
        uint4 u = row[lane + it * 32];
        const __nv_bfloat162* h = (const __nv_bfloat162*)&u;
        #pragma unroll
        for (int j = 0; j < 4; j++) {      // uint4 = 4 x bf16x2
            float2 f = __bfloat1622float2(h[j]);
            s = fmaf(f.x, f.x, s);
            s = fmaf(f.y, f.y, s);
        }
    }
    #pragma unroll
    for (int o = 16; o > 0; o >>= 1) s += __shfl_xor_sync(0xffffffffu, s, o);
    if (lane == 0) {
        g_xsq[n] = s;
        g_minbits[n] = 0x7F7FFFFFu;        // FLT_MAX bits
    }
}

// ----------------------------------------------------------------------------
// Kernel GEMM: pipelined bf16 mma.sync with fused row-min epilogue.
// Champion config (2 CTAs/SM x 8 warps): per kt: wait+sync, preload ks0
// frags, issue stage kt+2 into the ldmatrix latency window, 4 k16 groups with
// fragment double-buffering. kt loop unrolled x3 for compile-time selectors.
// msq staging AFTER the cp.async prologue. grid (98, 128), 256 threads.
// ----------------------------------------------------------------------------
__global__ void __launch_bounds__(256, 2) gemm_min_fb() {
    extern __shared__ char smem[];
    const int tid = threadIdx.x;
    const int wid = tid >> 5, lane = tid & 31;
    const int row_base = blockIdx.x * BM;
    const int n_base = blockIdx.y * BN;
    float* msq_s = (float*)(smem + SMEM_MSQ_OFF);
    const uint32_t sb = smem_u32(smem);

    // per-lane ldmatrix byte offsets within a tile, per k16 step ks=0..3
    uint32_t a_off[4], b_off[4];
    {
        uint32_t arow = (uint32_t)((lane & 15) * 128 + (lane >> 4) * 16);
        uint32_t brow = (uint32_t)((((lane >> 4) << 3) + (lane & 7)) * 128
                                   + ((lane >> 3) & 1) * 16);
        #pragma unroll
        for (int ks = 0; ks < 4; ks++) {
            a_off[ks] = swz128(arow + ks * 32);
            b_off[ks] = swz128(brow + ks * 32);
        }
    }
    const int mbw = (wid >> 2) * 64;   // warp m base
    const int nbw = (wid & 3) * 32;    // warp n base

    float acc[4][4][4];
    #pragma unroll
    for (int mi = 0; mi < 4; mi++)
        #pragma unroll
        for (int ni = 0; ni < 4; ni++)
            #pragma unroll
            for (int j = 0; j < 4; j++) acc[mi][ni][j] = 0.f;

    // one pipeline stage: A 128x64 + B 128x64 bf16 = 2048 x 16B transfers
    auto issue_stage = [&](int kt, int bsel) {
        uint32_t abase = sb + (uint32_t)(bsel * STAGE_BYTES);
        uint32_t bbase = abase + STAGE_A_BYTES;
        int kb = kt * BK;
        #pragma unroll
        for (int h = 0; h < 8; h++) {
            int i = tid + h * 256;
            int r = (i >> 3) & 127, s = i & 7;
            uint32_t doff = swz128((uint32_t)(r * 128 + s * 16));
            if (i < 1024) {
                cp_async16(abase + doff,
                           g_feats + (size_t)(row_base + r) * KDIM + kb + s * 8);
            } else {
                cp_async16(bbase + doff,
                           g_mb + (size_t)(n_base + r) * KDIM + kb + s * 8);
            }
        }
    };

    uint32_t ar[2][4][4], br[2][2][4];
    auto load_frags = [&](int buf, uint32_t awarp, uint32_t bwarp, int ks) {
        #pragma unroll
        for (int mi = 0; mi < 4; mi++)
            ldmx4(ar[buf][mi], awarp + (uint32_t)(mi * 16 * 128) + a_off[ks]);
        #pragma unroll
        for (int nb = 0; nb < 2; nb++)
            ldmx4(br[buf][nb], bwarp + (uint32_t)(nb * 16 * 128) + b_off[ks]);
    };
    auto do_mma = [&](int buf) {
        #pragma unroll
        for (int mi = 0; mi < 4; mi++)
            #pragma unroll
            for (int ni = 0; ni < 4; ni++)
                mma16816(acc[mi][ni], ar[buf][mi],
                         br[buf][ni >> 1][(ni & 1) * 2],
                         br[buf][ni >> 1][(ni & 1) * 2 + 1]);
    };

    // per-kt body, bsel = kt % STAGES as a compile-time constant at call site
    auto body = [&](int kt, int bsel) {
        asm volatile("cp.async.wait_group 1;" ::: "memory");
        __syncthreads();

        uint32_t abase = sb + (uint32_t)(bsel * STAGE_BYTES);
        uint32_t awarp = abase + (uint32_t)(mbw * 128);
        uint32_t bwarp = abase + STAGE_A_BYTES + (uint32_t)(nbw * 128);

        // preload ks0 fragments first...
        load_frags(0, awarp, bwarp, 0);

        // ...then fill the ldmatrix latency window with cp.async issue
        if (kt + 2 < NKT) issue_stage(kt + 2, (bsel + 2) % STAGES);
        asm volatile("cp.async.commit_group;" ::: "memory");

        #pragma unroll
        for (int ks = 0; ks < 4; ks++) {
            int cur = ks & 1, nxt = cur ^ 1;
            if (ks < 3) load_frags(nxt, awarp, bwarp, ks + 1);
            do_mma(cur);
        }
    };

    // prologue: 2 stages in flight, then stage msq (epilogue-only data)
    issue_stage(0, 0); asm volatile("cp.async.commit_group;" ::: "memory");
    issue_stage(1, 1); asm volatile("cp.async.commit_group;" ::: "memory");
    for (int i = tid; i < BN; i += 256) msq_s[i] = g_msq[n_base + i];

    #pragma unroll 1
    for (int kt0 = 0; kt0 < NKT; kt0 += 3) {   // NKT = 24, divisible by 3
        body(kt0 + 0, 0);
        body(kt0 + 1, 1);
        body(kt0 + 2, 2);
    }

    // epilogue: q = min_n (m_sq[n] - 2*dot); d2 = max(xsq + q, 0); atomicMin
    #pragma unroll
    for (int mi = 0; mi < 4; mi++) {
        float q0 = 3.4e38f, q1 = 3.4e38f;
        #pragma unroll
        for (int ni = 0; ni < 4; ni++) {
            int n = nbw + ni * 8 + (lane & 3) * 2;
            float ms0 = msq_s[n], ms1 = msq_s[n + 1];
            q0 = fminf(q0, fminf(fmaf(-2.f, acc[mi][ni][0], ms0),
                                 fmaf(-2.f, acc[mi][ni][1], ms1)));
            q1 = fminf(q1, fminf(fmaf(-2.f, acc[mi][ni][2], ms0),
                                 fmaf(-2.f, acc[mi][ni][3], ms1)));
        }
        q0 = fminf(q0, __shfl_xor_sync(0xffffffffu, q0, 1));
        q0 = fminf(q0, __shfl_xor_sync(0xffffffffu, q0, 2));
        q1 = fminf(q1, __shfl_xor_sync(0xffffffffu, q1, 1));
        q1 = fminf(q1, __shfl_xor_sync(0xffffffffu, q1, 2));
        if ((lane & 3) == 0) {
            int r0 = row_base + mbw + mi * 16 + (lane >> 2);
            int r1 = r0 + 8;
            float d0 = fmaxf(g_xsq[r0] + q0, 0.f);
            float d1 = fmaxf(g_xsq[r1] + q1, 0.f);
            atomicMin(&g_minbits[r0], __float_as_uint(d0));
            atomicMin(&g_minbits[r1], __float_as_uint(d1));
        }
    }
}

// ----------------------------------------------------------------------------
// Kernel 4: sqrt + bilinear 28->224 + per-batch max (atomicMax on f32 bits).
// grid (16 slices, 16 batches), 256 thr. Each block stages ONLY the <=5-row
// s28 window its 14 output rows touch.
// Output: [0, 16*50176) anomaly map, [16*50176, +16) pred scores.
// ----------------------------------------------------------------------------
__global__ void __launch_bounds__(256) finalize_kernel(float* __restrict__ out) {
    const int slice = blockIdx.x;          // 0..15 -> rows [slice*14, +14)
    const int b = blockIdx.y;
    const int tid = threadIdx.x;
    __shared__ float sw[6 * 28];           // staged source window
    __shared__ float sred[256];

    // source-row window for output rows [slice*14, slice*14+14):
    // sy in [1.75*slice - 0.4375, 1.75*slice + 1.1875]
    const int y_lo = max(0, (int)floorf(slice * 1.75f - 0.4375f));
    const int y_hi = min(27, (int)floorf(slice * 1.75f + 1.1875f) + 1);
    const int wrows = y_hi - y_lo + 1;     // <= 4

    if (tid < wrows * 28)
        sw[tid] = sqrtf(__uint_as_float(
            g_minbits[b * HW28 + (y_lo + tid / 28) * 28 + (tid % 28)]));
    __syncthreads();

    float mx = 0.f;
    float* omap = out + (size_t)b * OUTHW;
    const int p0 = slice * 3136, p1 = p0 + 3136;   // 14 rows x 224
    for (int p = p0 + tid; p < p1; p += 256) {
        int i = p / 224, j = p - (p / 224) * 224;
        float sy = i * 0.125f - 0.4375f;
        float sx = j * 0.125f - 0.4375f;
        float fy0 = floorf(sy), fx0 = floorf(sx);
        float wy = sy - fy0, wx = sx - fx0;
        int y0 = (int)fy0, x0 = (int)fx0;
        int y0c = max(0, min(27, y0)) - y_lo,  y1c = max(0, min(27, y0 + 1)) - y_lo;
        int x0c = max(0, min(27, x0)),         x1c = max(0, min(27, x0 + 1));
        float v00 = sw[y0c * 28 + x0c], v01 = sw[y0c * 28 + x1c];
        float v10 = sw[y1c * 28 + x0c], v11 = sw[y1c * 28 + x1c];
        float v = (1.f - wy) * ((1.f - wx) * v00 + wx * v01)
                +        wy  * ((1.f - wx) * v10 + wx * v11);
        omap[p] = v;
        mx = fmaxf(mx, v);
    }
    sred[tid] = mx;
    __syncthreads();
    for (int s = 128; s > 0; s >>= 1) {
        if (tid < s) sred[tid] = fmaxf(sred[tid], sred[tid + s]);
        __syncthreads();
    }
    if (tid == 0)  // values >= 0, so uint-bit compare == float compare
        atomicMax((unsigned*)&out[(size_t)BATCH * OUTHW + b],
                  __float_as_uint(sred[0]));
}

// ----------------------------------------------------------------------------
// Launch
// ----------------------------------------------------------------------------
extern "C" void kernel_launch(void* const* d_in, const int* in_sizes, int n_in,
                              void* d_out, int out_size) {
    const float* feat2 = (const float*)d_in[0];
    const float* feat3 = (const float*)d_in[1];
    const float* mbank = (const float*)d_in[2];
    float* out = (float*)d_out;

    cudaFuncSetAttribute(gemm_min_fb,
                         cudaFuncAttributeMaxDynamicSharedMemorySize, SMEM_TOTAL);

    prep_fused<<<PREP_BLOCKS, 256>>>(feat2, feat3, mbank, out);
    xsq_kernel<<<NROWS / 8, 256>>>();
    gemm_min_fb<<<dim3(NROWS / BM, MROWS / BN), 256, SMEM_TOTAL>>>();
    finalize_kernel<<<dim3(16, BATCH), 256>>>(out);
}